// round 2
// baseline (speedup 1.0000x reference)
#include <cuda_runtime.h>
#include <cstdint>
#include <cstddef>

#define BB 256
#define TT 512
#define NN 128
#define GO_IDX 1
#define EOS_IDX 2
#define NEGV -10000.0f

__device__ float g_alpha[(size_t)BB * TT * NN];
__device__ float g_score[BB];
__device__ int   g_bestTag[BB];

// lengths dtype self-detection: for little-endian int64, word[1] is the high
// word of lengths[0] == 0 (values in [T/2, T]); for int32 it's lengths[1] != 0.
__device__ __forceinline__ int load_len(const void* lp, int b) {
    const int* p32 = (const int*)lp;
    if (p32[1] == 0) return (int)((const long long*)lp)[b];
    return p32[b];
}

#define FWD_SMEM 68672

__global__ __launch_bounds__(512, 2)
void viterbi_forward_kernel(const float* __restrict__ unaries,
                            const float* __restrict__ trans,
                            const void*  __restrict__ lengths)
{
    extern __shared__ char smem[];
    float4* trF4     = (float4*)smem;
    float*  alpha_sh = (float*)(smem + 65536);
    float*  part     = (float*)(smem + 66048);
    float*  u_sh     = (float*)(smem + 68096);
    float*  redbuf   = (float*)(smem + 68608);

    const int b   = blockIdx.x;
    const int tid = threadIdx.x;
    const int g   = tid >> 7;
    const int cur = tid & 127;

    const int L = load_len(lengths, b);

    for (int i = tid; i < 32 * 128; i += 512) {
        int pc = i >> 7, c = i & 127;
        const float* tr = trans + c * NN + pc * 4;
        trF4[i] = make_float4(tr[0], tr[1], tr[2], tr[3]);
    }

    if (tid < 128) alpha_sh[tid] = (tid == GO_IDX) ? 0.0f : NEGV;
    __syncthreads();

    const float* urow = unaries + (size_t)b * TT * NN;
    float u = 0.0f;
    if (tid < 128) u = urow[cur];

    const float NEG_INF = __int_as_float(0xff800000);
    const int pcBase = g * 8;

    for (int t = 0; t < L; ++t) {
        float best = NEG_INF;
        #pragma unroll
        for (int j = 0; j < 8; ++j) {
            const int pc = pcBase + j;
            float4 a4 = *(const float4*)(alpha_sh + pc * 4);
            float4 t4 = trF4[pc * 128 + cur];
            best = fmaxf(best, a4.x + t4.x);
            best = fmaxf(best, a4.y + t4.y);
            best = fmaxf(best, a4.z + t4.z);
            best = fmaxf(best, a4.w + t4.w);
        }
        part[g * 128 + cur] = best;
        if (tid < 128) u_sh[cur] = u;
        __syncthreads();   // S1

        if (tid >= 128 && tid < 160) {
            const int lane = tid - 128;
            float4 uv = *(const float4*)(u_sh + lane * 4);
            float m = fmaxf(fmaxf(uv.x, uv.y), fmaxf(uv.z, uv.w));
            #pragma unroll
            for (int off = 16; off; off >>= 1)
                m = fmaxf(m, __shfl_xor_sync(0xffffffffu, m, off));
            float s = expf(uv.x - m) + expf(uv.y - m) + expf(uv.z - m) + expf(uv.w - m);
            #pragma unroll
            for (int off = 16; off; off >>= 1)
                s += __shfl_xor_sync(0xffffffffu, s, off);
            if (lane == 0) { redbuf[0] = m; redbuf[1] = logf(s); }
        }
        float mv = 0.0f;
        if (tid < 128) {
            mv = fmaxf(fmaxf(part[cur], part[128 + cur]),
                       fmaxf(part[256 + cur], part[384 + cur]));
        }
        __syncthreads();   // S2

        if (tid < 128) {
            float p = (u - redbuf[0]) - redbuf[1];   // match jax log_softmax rounding
            float a = mv + p;
            alpha_sh[cur] = a;
            g_alpha[((size_t)b * TT + t) * NN + cur] = a;
            if (t + 1 < L) u = urow[(size_t)(t + 1) * NN + cur];
        }
        __syncthreads();   // S3
    }

    if (tid < 128) {
        float tv = alpha_sh[cur] + trans[EOS_IDX * NN + cur];
        float bv = tv; int bi = cur;
        #pragma unroll
        for (int off = 16; off; off >>= 1) {
            float ov = __shfl_xor_sync(0xffffffffu, bv, off);
            int   oi = __shfl_xor_sync(0xffffffffu, bi, off);
            if (ov > bv || (ov == bv && oi < bi)) { bv = ov; bi = oi; }
        }
        if ((tid & 31) == 0) {
            int w = tid >> 5;
            redbuf[2 + w] = bv;
            ((int*)redbuf)[8 + w] = bi;
        }
    }
    __syncthreads();
    if (tid == 0) {
        float bv = redbuf[2]; int bi = ((int*)redbuf)[8];
        #pragma unroll
        for (int w = 1; w < 4; ++w) {
            float ov = redbuf[2 + w]; int oi = ((int*)redbuf)[8 + w];
            if (ov > bv) { bv = ov; bi = oi; }
        }
        g_score[b]   = bv;
        g_bestTag[b] = bi;
    }
}

#define BT_SMEM 65536

__global__ __launch_bounds__(256)
void viterbi_backtrace_kernel(const float* __restrict__ trans,
                              const void*  __restrict__ lengths,
                              void* __restrict__ outv,
                              int mode)
{
    extern __shared__ float4 trS[];
    const int tid = threadIdx.x;
    for (int i = tid; i < 32 * 128; i += 256)
        trS[i] = ((const float4*)trans)[i];
    __syncthreads();

    const int w    = tid >> 5;
    const int lane = tid & 31;
    const int b    = blockIdx.x * 8 + w;

    const int L = load_len(lengths, b);
    int cur = g_bestTag[b];

    float* outf = (float*)outv;
    int*   outi = (int*)outv;

    for (int t = L + lane; t < TT; t += 32) {
        if (mode) outf[b * TT + t] = 0.0f; else outi[b * TT + t] = 0;
    }
    if (lane == 0) {
        if (mode) {
            outf[b * TT + (L - 1)] = (float)cur;
            outf[BB * TT + b]      = g_score[b];
        } else {
            outi[b * TT + (L - 1)] = cur;
        }
    }

    const float4* arow = (const float4*)g_alpha + (size_t)b * TT * 32;
    const int t0 = L - 2;
    float4 buf0 = make_float4(0.f,0.f,0.f,0.f), buf1 = buf0;
    if (t0 >= 0)     buf0 = arow[(size_t)t0 * 32 + lane];
    if (t0 - 1 >= 0) buf1 = arow[(size_t)(t0 - 1) * 32 + lane];

    for (int t = t0; t >= 0; --t) {
        const int par = (t0 - t) & 1;
        float4 av = par ? buf1 : buf0;
        if (t - 2 >= 0) {
            float4 nb = arow[(size_t)(t - 2) * 32 + lane];
            if (par) buf1 = nb; else buf0 = nb;
        }
        float4 tv = trS[cur * 32 + lane];
        float v0 = av.x + tv.x, v1 = av.y + tv.y, v2 = av.z + tv.z, v3 = av.w + tv.w;
        float bv = v0; int bj = 0;
        if (v1 > bv) { bv = v1; bj = 1; }
        if (v2 > bv) { bv = v2; bj = 2; }
        if (v3 > bv) { bv = v3; bj = 3; }
        int bi = lane * 4 + bj;
        #pragma unroll
        for (int off = 16; off; off >>= 1) {
            float ov = __shfl_xor_sync(0xffffffffu, bv, off);
            int   oi = __shfl_xor_sync(0xffffffffu, bi, off);
            if (ov > bv || (ov == bv && oi < bi)) { bv = ov; bi = oi; }
        }
        cur = bi;
        if (lane == 0) {
            if (mode) outf[b * TT + t] = (float)cur; else outi[b * TT + t] = cur;
        }
    }
}

extern "C" void kernel_launch(void* const* d_in, const int* in_sizes, int n_in,
                              void* d_out, int out_size)
{
    const float* unaries = (const float*)d_in[0];
    const float* trans   = (const float*)d_in[1];
    const void*  lengths = d_in[2];

    cudaFuncSetAttribute(viterbi_forward_kernel,
                         cudaFuncAttributeMaxDynamicSharedMemorySize, FWD_SMEM);
    cudaFuncSetAttribute(viterbi_backtrace_kernel,
                         cudaFuncAttributeMaxDynamicSharedMemorySize, BT_SMEM);

    // Output layout: concat(preds[B,T], scores[B]) as f32 if out_size matches,
    // otherwise preds-only as int32.
    const int mode = (out_size == BB * TT + BB) ? 1 : 0;

    viterbi_forward_kernel<<<BB, 512, FWD_SMEM>>>(unaries, trans, lengths);
    viterbi_backtrace_kernel<<<32, 256, BT_SMEM>>>(trans, lengths, d_out, mode);
}